// round 12
// baseline (speedup 1.0000x reference)
#include <cuda_runtime.h>

// ---------------------------------------------------------------------------
// RgbNet, R12: R11 fused kernel, 1024 threads/block (32 warps) for 2x the
// latency-hiding at the same 128-ray / 198KB-smem tile.
//  Phase 0: pack W1/W2 global -> B-fragment hi/lo smem (LDG->split->STS.128).
//  Phase E: encode 128 rays x 6 levels (corner cache) -> F[128][132] smem.
//  Layers:  mma.sync m16n8k8 tf32, D = Ahi*Bhi + Ahi*Blo (A pre-rounded);
//           warp = 1 M-tile x 2 N-tiles (32 warps); W3 packed during layer 2.
//  Layer 4: 8 threads per ray, shuffle reduce.
// ---------------------------------------------------------------------------

namespace {
constexpr int NRAYS   = 16384;
constexpr int NSAMP   = 300;
constexpr unsigned HSIZE = 1u << 19;
constexpr unsigned HMASK = HSIZE - 1u;

constexpr int THREADS = 1024;    // 32 warps
constexpr int RPB     = 128;     // rays per block
constexpr int BLOCKS  = NRAYS / RPB;     // 128

// packed weight sizes (uint4 units): (K/8) * 8 ntiles * 32 lanes
constexpr int W1_PK = 15 * 8 * 32;   // 3840
constexpr int W2_PK = 8 * 8 * 32;    // 2048
constexpr int W3_PK = 8 * 8 * 32;    // 2048

// shared layout (float offsets)
constexpr int OFF_F   = 0;                   // F  [128][132] (feats / h2)
constexpr int OFF_H   = OFF_F + 128 * 132;   // H  [128][68]  (h1 / h3)
constexpr int OFF_W0  = OFF_H + 128 * 68;    // Wbuf0: 15360 fl (W1, then W3)
constexpr int OFF_W1B = OFF_W0 + 15360;      // Wbuf1: 8192 fl (W2)
constexpr int OFF_BS  = OFF_W1B + 8192;      // b1,b2,b3 (192) b4 (4) W4 (192)
constexpr int SH_FLOATS = OFF_BS + 388;      // 49540 fl = 198160 B
}

// ---- tf32 helpers -----------------------------------------------------------
__device__ __forceinline__ float tf32r(float v) {
    unsigned u;
    asm("cvt.rna.tf32.f32 %0, %1;" : "=r"(u) : "f"(v));
    return __uint_as_float(u);
}
__device__ __forceinline__ void split_tf32(float v, unsigned& hi, unsigned& lo) {
    asm("cvt.rna.tf32.f32 %0, %1;" : "=r"(hi) : "f"(v));
    const float lof = v - __uint_as_float(hi);
    asm("cvt.rna.tf32.f32 %0, %1;" : "=r"(lo) : "f"(lof));
}
__device__ __forceinline__ void mma_tf32(float* c, const unsigned* a,
                                         const unsigned b0, const unsigned b1) {
    asm volatile(
        "mma.sync.aligned.m16n8k8.row.col.f32.tf32.tf32.f32 "
        "{%0,%1,%2,%3}, {%4,%5,%6,%7}, {%8,%9}, {%0,%1,%2,%3};"
        : "+f"(c[0]), "+f"(c[1]), "+f"(c[2]), "+f"(c[3])
        : "r"(a[0]), "r"(a[1]), "r"(a[2]), "r"(a[3]), "r"(b0), "r"(b1));
}

// pack one uint4 slot of weight matrix Ws[N][K] into B-fragment hi/lo order
template <int K>
__device__ __forceinline__ void pack_slot(const float* __restrict__ Ws,
                                          uint4* __restrict__ dst, int u) {
    const int kt = u >> 8, rem = u & 255;
    const int nt = rem >> 5, lane = rem & 31;
    const int g = lane >> 2, tg = lane & 3;
    const int k0 = kt * 8 + tg, n = nt * 8 + g;
    const float v0 = __ldg(Ws + n * K + k0);
    const float v1 = __ldg(Ws + n * K + k0 + 4);
    unsigned h0, l0, h1, l1;
    split_tf32(v0, h0, l0);
    split_tf32(v1, h1, l1);
    dst[u] = make_uint4(h0, h1, l0, l1);
}

// One layer: warp covers M-tile mt (rows 16mt..16mt+15) x N-tiles {2np,2np+1}.
// actIn values already tf32-rounded. actOut stride 68.
template <int KSTEPS, int STRIDE>
__device__ __forceinline__ void mma_layer(const float* __restrict__ actIn,
                                          const float* __restrict__ wb,
                                          const float* __restrict__ bias,
                                          float*       __restrict__ actOut,
                                          int mt, int np, int lane) {
    const int g = lane >> 2, tg = lane & 3;
    const int rbase = mt * 16 + g;

    float acc[2][4];
    #pragma unroll
    for (int j = 0; j < 2; j++) {
        const int n0 = (np * 2 + j) * 8 + 2 * tg;
        const float bc0 = bias[n0], bc1 = bias[n0 + 1];
        acc[j][0] = bc0; acc[j][1] = bc1;
        acc[j][2] = bc0; acc[j][3] = bc1;
    }

    const unsigned* a0 = reinterpret_cast<const unsigned*>(
        actIn + (size_t)rbase * STRIDE);
    const unsigned* a1 = a0 + 8 * STRIDE;

    #pragma unroll
    for (int kt = 0; kt < KSTEPS; kt++) {
        const int kb = kt * 8;
        unsigned ah[4];
        ah[0] = a0[kb + tg];     ah[1] = a1[kb + tg];
        ah[2] = a0[kb + tg + 4]; ah[3] = a1[kb + tg + 4];

        #pragma unroll
        for (int j = 0; j < 2; j++) {
            const uint4 bw = *reinterpret_cast<const uint4*>(
                wb + ((size_t)((kt * 8 + np * 2 + j) * 32) + lane) * 4);
            mma_tf32(acc[j], ah, bw.x, bw.y);   // Ahi * Bhi
            mma_tf32(acc[j], ah, bw.z, bw.w);   // Ahi * Blo
        }
    }

    const int r0 = rbase, r1 = rbase + 8;
    #pragma unroll
    for (int j = 0; j < 2; j++) {
        const int n0 = (np * 2 + j) * 8 + 2 * tg;
        *reinterpret_cast<float2*>(actOut + r0 * 68 + n0) =
            make_float2(tf32r(fmaxf(acc[j][0], 0.0f)),
                        tf32r(fmaxf(acc[j][1], 0.0f)));
        *reinterpret_cast<float2*>(actOut + r1 * 68 + n0) =
            make_float2(tf32r(fmaxf(acc[j][2], 0.0f)),
                        tf32r(fmaxf(acc[j][3], 0.0f)));
    }
}

__global__ __launch_bounds__(THREADS)
void rgbnet_fused(const float* __restrict__ x,        // [N,4]
                  const int*   __restrict__ ifirst,   // [N]
                  const float* __restrict__ emb,      // [6,2^19,4]
                  const float* __restrict__ W1, const float* __restrict__ b1,
                  const float* __restrict__ W2, const float* __restrict__ b2,
                  const float* __restrict__ W3, const float* __restrict__ b3,
                  const float* __restrict__ W4, const float* __restrict__ b4,
                  float* __restrict__ out)             // [N,3]
{
    extern __shared__ float sh[];
    float* F   = sh + OFF_F;
    float* H   = sh + OFF_H;
    float* W0  = sh + OFF_W0;
    float* W1B = sh + OFF_W1B;
    float* BS  = sh + OFF_BS;

    const int tid  = threadIdx.x;
    const int ray0 = blockIdx.x * RPB;

    // ---- Phase 0: pack W1 -> W0, W2 -> W1B; biases + W4 --------------------
    for (int u = tid; u < W1_PK; u += THREADS)
        pack_slot<120>(W1, reinterpret_cast<uint4*>(W0), u);
    for (int u = tid; u < W2_PK; u += THREADS)
        pack_slot<64>(W2, reinterpret_cast<uint4*>(W1B), u);
    if (tid < 64) {
        BS[tid]       = __ldg(b1 + tid);
        BS[64 + tid]  = __ldg(b2 + tid);
        BS[128 + tid] = __ldg(b3 + tid);
    }
    if (tid < 4)   BS[192 + tid] = (tid < 3) ? __ldg(b4 + tid) : 0.0f;
    if (tid < 192) BS[196 + tid] = __ldg(W4 + tid);

    // ---- Phase E: encode -> F[128][132] (768 tasks, one sweep) -------------
    if (tid < 6 * RPB) {
        const int l   = tid >> 7;            // level, warp-uniform
        const int col = tid & 127;
        const int ray = ray0 + col;

        const float4 xr  = __ldg(reinterpret_cast<const float4*>(x) + ray);
        const int    if0 = __ldg(ifirst + ray);

        const int   R   = 4 << l;
        const float fR  = (float)R;
        const int   Rp1 = R + 1;
        const float4* __restrict__ tab =
            reinterpret_cast<const float4*>(emb) + (size_t)l * HSIZE;

        int    prev_key = -1;
        float4 cc[8];

        #pragma unroll
        for (int s = 0; s < 5; s++) {
            int sc = if0 + s - 2;
            sc = sc < 0 ? 0 : (sc > NSAMP - 1 ? NSAMP - 1 : sc);
            const float tt  = (float)sc * (1.0f / 299.0f);
            const float omt = 1.0f - tt;
            const float px = xr.x * omt + xr.z * tt;
            const float py = xr.y * omt + xr.w * tt;
            const float pz = tt;

            const float fx = px * fR, fy = py * fR, fz = pz * fR;
            const float flx = floorf(fx), fly = floorf(fy), flz = floorf(fz);
            const int ix = (int)flx, iy = (int)fly, iz = (int)flz;
            const float wx = fx - flx, wy = fy - fly, wz = fz - flz;

            const int key = ix | (iy << 10) | (iz << 20);
            if (key != prev_key) {
                prev_key = key;
                #pragma unroll
                for (int c = 0; c < 8; c++) {
                    const int bx = (c >> 2) & 1, by = (c >> 1) & 1, bz = c & 1;
                    int cx = ix + bx; cx = cx > R ? R : cx;
                    int cy = iy + by; cy = cy > R ? R : cy;
                    int cz = iz + bz; cz = cz > R ? R : cz;
                    const unsigned id_dense =
                        (unsigned)(cx + cy * Rp1 + cz * Rp1 * Rp1);
                    const unsigned id_hash =
                        ((unsigned)cx ^ ((unsigned)cy * 2654435761u)
                                     ^ ((unsigned)cz * 805459861u)) & HMASK;
                    const unsigned idx = (l == 5) ? id_hash : id_dense;
                    cc[c] = __ldg(tab + idx);
                }
            }

            float ax = 0.f, ay = 0.f, az = 0.f, aw = 0.f;
            #pragma unroll
            for (int c = 0; c < 8; c++) {
                const int bx = (c >> 2) & 1, by = (c >> 1) & 1, bz = c & 1;
                const float wgt = (bx ? wx : 1.0f - wx)
                                * (by ? wy : 1.0f - wy)
                                * (bz ? wz : 1.0f - wz);
                ax = fmaf(wgt, cc[c].x, ax);
                ay = fmaf(wgt, cc[c].y, ay);
                az = fmaf(wgt, cc[c].z, az);
                aw = fmaf(wgt, cc[c].w, aw);
            }

            const int kb = (s * 6 + l) * 4;
            *reinterpret_cast<float4*>(F + col * 132 + kb) =
                make_float4(tf32r(ax), tf32r(ay), tf32r(az), tf32r(aw));
        }
    }
    __syncthreads();     // F feats + W1/W2 + biases visible

    const int lane = tid & 31;
    const int warp = tid >> 5;              // 0..31
    const int mt   = warp & 7;              // M-tile (rays 16mt..16mt+15)
    const int np   = warp >> 3;             // N-pair (outs 16np..16np+15)

    // ---- layer 1: F (K=120) -> H --------------------------------------------
    mma_layer<15, 132>(F, W0, BS, H, mt, np, lane);
    __syncthreads();     // H visible; W0 (W1) dead

    // pack W3 into W0 (overlaps layer 2 in the instruction stream)
    for (int u = tid; u < W3_PK; u += THREADS)
        pack_slot<64>(W3, reinterpret_cast<uint4*>(W0), u);

    // ---- layer 2: H -> F ------------------------------------------------------
    mma_layer<8, 68>(H, W1B, BS + 64, F, mt, np, lane);
    __syncthreads();     // h2 visible AND W3 visible

    // ---- layer 3: F -> H ------------------------------------------------------
    mma_layer<8, 68>(F, W0, BS + 128, H, mt, np, lane);
    __syncthreads();

    // ---- layer 4: 64 -> 3, 8 threads per ray ----------------------------------
    {
        const int ray = tid >> 3;            // 0..127
        const int kq  = tid & 7;             // k-eighth
        const float* hrow = H + ray * 68 + kq * 8;
        const float* W4s  = BS + 196 + kq * 8;
        float a0 = 0.f, a1 = 0.f, a2 = 0.f;
        #pragma unroll
        for (int k = 0; k < 8; k++) {
            const float hv = hrow[k];
            a0 = fmaf(hv, W4s[k],       a0);
            a1 = fmaf(hv, W4s[64 + k],  a1);
            a2 = fmaf(hv, W4s[128 + k], a2);
        }
        a0 += __shfl_xor_sync(0xffffffffu, a0, 1);
        a1 += __shfl_xor_sync(0xffffffffu, a1, 1);
        a2 += __shfl_xor_sync(0xffffffffu, a2, 1);
        a0 += __shfl_xor_sync(0xffffffffu, a0, 2);
        a1 += __shfl_xor_sync(0xffffffffu, a1, 2);
        a2 += __shfl_xor_sync(0xffffffffu, a2, 2);
        a0 += __shfl_xor_sync(0xffffffffu, a0, 4);
        a1 += __shfl_xor_sync(0xffffffffu, a1, 4);
        a2 += __shfl_xor_sync(0xffffffffu, a2, 4);
        if (kq == 0) {
            float* o = out + (size_t)(ray0 + ray) * 3;
            o[0] = a0 + BS[192];
            o[1] = a1 + BS[193];
            o[2] = a2 + BS[194];
        }
    }
}

extern "C" void kernel_launch(void* const* d_in, const int* in_sizes, int n_in,
                              void* d_out, int out_size) {
    const float* x    = (const float*)d_in[0];
    const int*   idxf = (const int*)  d_in[1];
    const float* emb  = (const float*)d_in[2];
    const float* W1   = (const float*)d_in[3];
    const float* b1   = (const float*)d_in[4];
    const float* W2   = (const float*)d_in[5];
    const float* b2   = (const float*)d_in[6];
    const float* W3   = (const float*)d_in[7];
    const float* b3   = (const float*)d_in[8];
    const float* W4   = (const float*)d_in[9];
    const float* b4   = (const float*)d_in[10];
    float* out = (float*)d_out;

    const size_t shbytes = (size_t)SH_FLOATS * sizeof(float);   // 198160 B
    cudaFuncSetAttribute(rgbnet_fused,
                         cudaFuncAttributeMaxDynamicSharedMemorySize,
                         (int)shbytes);
    rgbnet_fused<<<BLOCKS, THREADS, shbytes>>>(
        x, idxf, emb, W1, b1, W2, b2, W3, b3, W4, b4, out);
}

// round 13
// speedup vs baseline: 1.0014x; 1.0014x over previous
#include <cuda_runtime.h>

// ---------------------------------------------------------------------------
// RgbNet, R12: R11 fused kernel, 1024 threads/block (32 warps) for 2x the
// latency-hiding at the same 128-ray / 198KB-smem tile.
//  Phase 0: pack W1/W2 global -> B-fragment hi/lo smem (LDG->split->STS.128).
//  Phase E: encode 128 rays x 6 levels (corner cache) -> F[128][132] smem.
//  Layers:  mma.sync m16n8k8 tf32, D = Ahi*Bhi + Ahi*Blo (A pre-rounded);
//           warp = 1 M-tile x 2 N-tiles (32 warps); W3 packed during layer 2.
//  Layer 4: 8 threads per ray, shuffle reduce.
// ---------------------------------------------------------------------------

namespace {
constexpr int NRAYS   = 16384;
constexpr int NSAMP   = 300;
constexpr unsigned HSIZE = 1u << 19;
constexpr unsigned HMASK = HSIZE - 1u;

constexpr int THREADS = 1024;    // 32 warps
constexpr int RPB     = 128;     // rays per block
constexpr int BLOCKS  = NRAYS / RPB;     // 128

// packed weight sizes (uint4 units): (K/8) * 8 ntiles * 32 lanes
constexpr int W1_PK = 15 * 8 * 32;   // 3840
constexpr int W2_PK = 8 * 8 * 32;    // 2048
constexpr int W3_PK = 8 * 8 * 32;    // 2048

// shared layout (float offsets)
constexpr int OFF_F   = 0;                   // F  [128][132] (feats / h2)
constexpr int OFF_H   = OFF_F + 128 * 132;   // H  [128][68]  (h1 / h3)
constexpr int OFF_W0  = OFF_H + 128 * 68;    // Wbuf0: 15360 fl (W1, then W3)
constexpr int OFF_W1B = OFF_W0 + 15360;      // Wbuf1: 8192 fl (W2)
constexpr int OFF_BS  = OFF_W1B + 8192;      // b1,b2,b3 (192) b4 (4) W4 (192)
constexpr int SH_FLOATS = OFF_BS + 388;      // 49540 fl = 198160 B
}

// ---- tf32 helpers -----------------------------------------------------------
__device__ __forceinline__ float tf32r(float v) {
    unsigned u;
    asm("cvt.rna.tf32.f32 %0, %1;" : "=r"(u) : "f"(v));
    return __uint_as_float(u);
}
__device__ __forceinline__ void split_tf32(float v, unsigned& hi, unsigned& lo) {
    asm("cvt.rna.tf32.f32 %0, %1;" : "=r"(hi) : "f"(v));
    const float lof = v - __uint_as_float(hi);
    asm("cvt.rna.tf32.f32 %0, %1;" : "=r"(lo) : "f"(lof));
}
__device__ __forceinline__ void mma_tf32(float* c, const unsigned* a,
                                         const unsigned b0, const unsigned b1) {
    asm volatile(
        "mma.sync.aligned.m16n8k8.row.col.f32.tf32.tf32.f32 "
        "{%0,%1,%2,%3}, {%4,%5,%6,%7}, {%8,%9}, {%0,%1,%2,%3};"
        : "+f"(c[0]), "+f"(c[1]), "+f"(c[2]), "+f"(c[3])
        : "r"(a[0]), "r"(a[1]), "r"(a[2]), "r"(a[3]), "r"(b0), "r"(b1));
}

// pack one uint4 slot of weight matrix Ws[N][K] into B-fragment hi/lo order
template <int K>
__device__ __forceinline__ void pack_slot(const float* __restrict__ Ws,
                                          uint4* __restrict__ dst, int u) {
    const int kt = u >> 8, rem = u & 255;
    const int nt = rem >> 5, lane = rem & 31;
    const int g = lane >> 2, tg = lane & 3;
    const int k0 = kt * 8 + tg, n = nt * 8 + g;
    const float v0 = __ldg(Ws + n * K + k0);
    const float v1 = __ldg(Ws + n * K + k0 + 4);
    unsigned h0, l0, h1, l1;
    split_tf32(v0, h0, l0);
    split_tf32(v1, h1, l1);
    dst[u] = make_uint4(h0, h1, l0, l1);
}

// One layer: warp covers M-tile mt (rows 16mt..16mt+15) x N-tiles {2np,2np+1}.
// actIn values already tf32-rounded. actOut stride 68.
template <int KSTEPS, int STRIDE>
__device__ __forceinline__ void mma_layer(const float* __restrict__ actIn,
                                          const float* __restrict__ wb,
                                          const float* __restrict__ bias,
                                          float*       __restrict__ actOut,
                                          int mt, int np, int lane) {
    const int g = lane >> 2, tg = lane & 3;
    const int rbase = mt * 16 + g;

    float acc[2][4];
    #pragma unroll
    for (int j = 0; j < 2; j++) {
        const int n0 = (np * 2 + j) * 8 + 2 * tg;
        const float bc0 = bias[n0], bc1 = bias[n0 + 1];
        acc[j][0] = bc0; acc[j][1] = bc1;
        acc[j][2] = bc0; acc[j][3] = bc1;
    }

    const unsigned* a0 = reinterpret_cast<const unsigned*>(
        actIn + (size_t)rbase * STRIDE);
    const unsigned* a1 = a0 + 8 * STRIDE;

    #pragma unroll
    for (int kt = 0; kt < KSTEPS; kt++) {
        const int kb = kt * 8;
        unsigned ah[4];
        ah[0] = a0[kb + tg];     ah[1] = a1[kb + tg];
        ah[2] = a0[kb + tg + 4]; ah[3] = a1[kb + tg + 4];

        #pragma unroll
        for (int j = 0; j < 2; j++) {
            const uint4 bw = *reinterpret_cast<const uint4*>(
                wb + ((size_t)((kt * 8 + np * 2 + j) * 32) + lane) * 4);
            mma_tf32(acc[j], ah, bw.x, bw.y);   // Ahi * Bhi
            mma_tf32(acc[j], ah, bw.z, bw.w);   // Ahi * Blo
        }
    }

    const int r0 = rbase, r1 = rbase + 8;
    #pragma unroll
    for (int j = 0; j < 2; j++) {
        const int n0 = (np * 2 + j) * 8 + 2 * tg;
        *reinterpret_cast<float2*>(actOut + r0 * 68 + n0) =
            make_float2(tf32r(fmaxf(acc[j][0], 0.0f)),
                        tf32r(fmaxf(acc[j][1], 0.0f)));
        *reinterpret_cast<float2*>(actOut + r1 * 68 + n0) =
            make_float2(tf32r(fmaxf(acc[j][2], 0.0f)),
                        tf32r(fmaxf(acc[j][3], 0.0f)));
    }
}

__global__ __launch_bounds__(THREADS)
void rgbnet_fused(const float* __restrict__ x,        // [N,4]
                  const int*   __restrict__ ifirst,   // [N]
                  const float* __restrict__ emb,      // [6,2^19,4]
                  const float* __restrict__ W1, const float* __restrict__ b1,
                  const float* __restrict__ W2, const float* __restrict__ b2,
                  const float* __restrict__ W3, const float* __restrict__ b3,
                  const float* __restrict__ W4, const float* __restrict__ b4,
                  float* __restrict__ out)             // [N,3]
{
    extern __shared__ float sh[];
    float* F   = sh + OFF_F;
    float* H   = sh + OFF_H;
    float* W0  = sh + OFF_W0;
    float* W1B = sh + OFF_W1B;
    float* BS  = sh + OFF_BS;

    const int tid  = threadIdx.x;
    const int ray0 = blockIdx.x * RPB;

    // ---- Phase 0: pack W1 -> W0, W2 -> W1B; biases + W4 --------------------
    for (int u = tid; u < W1_PK; u += THREADS)
        pack_slot<120>(W1, reinterpret_cast<uint4*>(W0), u);
    for (int u = tid; u < W2_PK; u += THREADS)
        pack_slot<64>(W2, reinterpret_cast<uint4*>(W1B), u);
    if (tid < 64) {
        BS[tid]       = __ldg(b1 + tid);
        BS[64 + tid]  = __ldg(b2 + tid);
        BS[128 + tid] = __ldg(b3 + tid);
    }
    if (tid < 4)   BS[192 + tid] = (tid < 3) ? __ldg(b4 + tid) : 0.0f;
    if (tid < 192) BS[196 + tid] = __ldg(W4 + tid);

    // ---- Phase E: encode -> F[128][132] (768 tasks, one sweep) -------------
    if (tid < 6 * RPB) {
        const int l   = tid >> 7;            // level, warp-uniform
        const int col = tid & 127;
        const int ray = ray0 + col;

        const float4 xr  = __ldg(reinterpret_cast<const float4*>(x) + ray);
        const int    if0 = __ldg(ifirst + ray);

        const int   R   = 4 << l;
        const float fR  = (float)R;
        const int   Rp1 = R + 1;
        const float4* __restrict__ tab =
            reinterpret_cast<const float4*>(emb) + (size_t)l * HSIZE;

        int    prev_key = -1;
        float4 cc[8];

        #pragma unroll
        for (int s = 0; s < 5; s++) {
            int sc = if0 + s - 2;
            sc = sc < 0 ? 0 : (sc > NSAMP - 1 ? NSAMP - 1 : sc);
            const float tt  = (float)sc * (1.0f / 299.0f);
            const float omt = 1.0f - tt;
            const float px = xr.x * omt + xr.z * tt;
            const float py = xr.y * omt + xr.w * tt;
            const float pz = tt;

            const float fx = px * fR, fy = py * fR, fz = pz * fR;
            const float flx = floorf(fx), fly = floorf(fy), flz = floorf(fz);
            const int ix = (int)flx, iy = (int)fly, iz = (int)flz;
            const float wx = fx - flx, wy = fy - fly, wz = fz - flz;

            const int key = ix | (iy << 10) | (iz << 20);
            if (key != prev_key) {
                prev_key = key;
                #pragma unroll
                for (int c = 0; c < 8; c++) {
                    const int bx = (c >> 2) & 1, by = (c >> 1) & 1, bz = c & 1;
                    int cx = ix + bx; cx = cx > R ? R : cx;
                    int cy = iy + by; cy = cy > R ? R : cy;
                    int cz = iz + bz; cz = cz > R ? R : cz;
                    const unsigned id_dense =
                        (unsigned)(cx + cy * Rp1 + cz * Rp1 * Rp1);
                    const unsigned id_hash =
                        ((unsigned)cx ^ ((unsigned)cy * 2654435761u)
                                     ^ ((unsigned)cz * 805459861u)) & HMASK;
                    const unsigned idx = (l == 5) ? id_hash : id_dense;
                    cc[c] = __ldg(tab + idx);
                }
            }

            float ax = 0.f, ay = 0.f, az = 0.f, aw = 0.f;
            #pragma unroll
            for (int c = 0; c < 8; c++) {
                const int bx = (c >> 2) & 1, by = (c >> 1) & 1, bz = c & 1;
                const float wgt = (bx ? wx : 1.0f - wx)
                                * (by ? wy : 1.0f - wy)
                                * (bz ? wz : 1.0f - wz);
                ax = fmaf(wgt, cc[c].x, ax);
                ay = fmaf(wgt, cc[c].y, ay);
                az = fmaf(wgt, cc[c].z, az);
                aw = fmaf(wgt, cc[c].w, aw);
            }

            const int kb = (s * 6 + l) * 4;
            *reinterpret_cast<float4*>(F + col * 132 + kb) =
                make_float4(tf32r(ax), tf32r(ay), tf32r(az), tf32r(aw));
        }
    }
    __syncthreads();     // F feats + W1/W2 + biases visible

    const int lane = tid & 31;
    const int warp = tid >> 5;              // 0..31
    const int mt   = warp & 7;              // M-tile (rays 16mt..16mt+15)
    const int np   = warp >> 3;             // N-pair (outs 16np..16np+15)

    // ---- layer 1: F (K=120) -> H --------------------------------------------
    mma_layer<15, 132>(F, W0, BS, H, mt, np, lane);
    __syncthreads();     // H visible; W0 (W1) dead

    // pack W3 into W0 (overlaps layer 2 in the instruction stream)
    for (int u = tid; u < W3_PK; u += THREADS)
        pack_slot<64>(W3, reinterpret_cast<uint4*>(W0), u);

    // ---- layer 2: H -> F ------------------------------------------------------
    mma_layer<8, 68>(H, W1B, BS + 64, F, mt, np, lane);
    __syncthreads();     // h2 visible AND W3 visible

    // ---- layer 3: F -> H ------------------------------------------------------
    mma_layer<8, 68>(F, W0, BS + 128, H, mt, np, lane);
    __syncthreads();

    // ---- layer 4: 64 -> 3, 8 threads per ray ----------------------------------
    {
        const int ray = tid >> 3;            // 0..127
        const int kq  = tid & 7;             // k-eighth
        const float* hrow = H + ray * 68 + kq * 8;
        const float* W4s  = BS + 196 + kq * 8;
        float a0 = 0.f, a1 = 0.f, a2 = 0.f;
        #pragma unroll
        for (int k = 0; k < 8; k++) {
            const float hv = hrow[k];
            a0 = fmaf(hv, W4s[k],       a0);
            a1 = fmaf(hv, W4s[64 + k],  a1);
            a2 = fmaf(hv, W4s[128 + k], a2);
        }
        a0 += __shfl_xor_sync(0xffffffffu, a0, 1);
        a1 += __shfl_xor_sync(0xffffffffu, a1, 1);
        a2 += __shfl_xor_sync(0xffffffffu, a2, 1);
        a0 += __shfl_xor_sync(0xffffffffu, a0, 2);
        a1 += __shfl_xor_sync(0xffffffffu, a1, 2);
        a2 += __shfl_xor_sync(0xffffffffu, a2, 2);
        a0 += __shfl_xor_sync(0xffffffffu, a0, 4);
        a1 += __shfl_xor_sync(0xffffffffu, a1, 4);
        a2 += __shfl_xor_sync(0xffffffffu, a2, 4);
        if (kq == 0) {
            float* o = out + (size_t)(ray0 + ray) * 3;
            o[0] = a0 + BS[192];
            o[1] = a1 + BS[193];
            o[2] = a2 + BS[194];
        }
    }
}

extern "C" void kernel_launch(void* const* d_in, const int* in_sizes, int n_in,
                              void* d_out, int out_size) {
    const float* x    = (const float*)d_in[0];
    const int*   idxf = (const int*)  d_in[1];
    const float* emb  = (const float*)d_in[2];
    const float* W1   = (const float*)d_in[3];
    const float* b1   = (const float*)d_in[4];
    const float* W2   = (const float*)d_in[5];
    const float* b2   = (const float*)d_in[6];
    const float* W3   = (const float*)d_in[7];
    const float* b3   = (const float*)d_in[8];
    const float* W4   = (const float*)d_in[9];
    const float* b4   = (const float*)d_in[10];
    float* out = (float*)d_out;

    const size_t shbytes = (size_t)SH_FLOATS * sizeof(float);   // 198160 B
    cudaFuncSetAttribute(rgbnet_fused,
                         cudaFuncAttributeMaxDynamicSharedMemorySize,
                         (int)shbytes);
    rgbnet_fused<<<BLOCKS, THREADS, shbytes>>>(
        x, idxf, emb, W1, b1, W2, b2, W3, b3, W4, b4, out);
}

// round 14
// speedup vs baseline: 1.0111x; 1.0097x over previous
#include <cuda_runtime.h>

// ---------------------------------------------------------------------------
// RgbNet, R13: B-operands moved to L1-cached GLOBAL -> 2 blocks/SM overlap.
//  K0 pack:  tiny kernel, packs W1/W2/W3 into B-fragment hi/lo uint4 order
//            (g_Wpack, 127KB) once.
//  K1 fused: 293 blocks x 512 thr x 56 rays (64-col padded tile).
//            Phase E: encode 64 cols x 6 levels -> F[64][132] smem.
//            Layers: mma.sync m16n8k8 tf32, D = Ahi*Bhi + Ahi*Blo;
//                    A from smem, B via __ldg (L1-resident, shared lines).
//            Layer 4: 8 threads/ray shuffle reduce.
//            smem 53KB, <=64 regs -> 2 blocks/SM, phases overlap.
// ---------------------------------------------------------------------------

namespace {
constexpr int NRAYS   = 16384;
constexpr int NSAMP   = 300;
constexpr unsigned HSIZE = 1u << 19;
constexpr unsigned HMASK = HSIZE - 1u;

constexpr int THREADS = 512;     // 16 warps
constexpr int RPB     = 56;      // valid rays per block (64-col tile)
constexpr int BLOCKS  = (NRAYS + RPB - 1) / RPB;   // 293

// packed weight sizes (uint4 units): (K/8) * 8 ntiles * 32 lanes
constexpr int W1_PK = 15 * 8 * 32;   // 3840
constexpr int W2_PK = 8 * 8 * 32;    // 2048
constexpr int W3_PK = 8 * 8 * 32;    // 2048
constexpr int WPK_TOTAL = W1_PK + W2_PK + W3_PK;   // 7936

// shared layout (float offsets)
constexpr int OFF_F  = 0;                   // F [64][132] (feats / h2)
constexpr int OFF_H  = OFF_F + 64 * 132;    // H [64][68]  (h1 / h3)
constexpr int OFF_BS = OFF_H + 64 * 68;     // b1,b2,b3 (192) b4 (4) W4 (192)
constexpr int SH_FLOATS = OFF_BS + 388;     // 13188 fl = 52752 B
}

__device__ uint4 g_Wpack[WPK_TOTAL];

// ---- tf32 helpers -----------------------------------------------------------
__device__ __forceinline__ float tf32r(float v) {
    unsigned u;
    asm("cvt.rna.tf32.f32 %0, %1;" : "=r"(u) : "f"(v));
    return __uint_as_float(u);
}
__device__ __forceinline__ void split_tf32(float v, unsigned& hi, unsigned& lo) {
    asm("cvt.rna.tf32.f32 %0, %1;" : "=r"(hi) : "f"(v));
    const float lof = v - __uint_as_float(hi);
    asm("cvt.rna.tf32.f32 %0, %1;" : "=r"(lo) : "f"(lof));
}
__device__ __forceinline__ void mma_tf32(float* c, const unsigned* a,
                                         const unsigned b0, const unsigned b1) {
    asm volatile(
        "mma.sync.aligned.m16n8k8.row.col.f32.tf32.tf32.f32 "
        "{%0,%1,%2,%3}, {%4,%5,%6,%7}, {%8,%9}, {%0,%1,%2,%3};"
        : "+f"(c[0]), "+f"(c[1]), "+f"(c[2]), "+f"(c[3])
        : "r"(a[0]), "r"(a[1]), "r"(a[2]), "r"(a[3]), "r"(b0), "r"(b1));
}

// ===========================================================================
// Kernel 0: pack weights into B-fragment hi/lo uint4 order (once)
// ===========================================================================
__global__ __launch_bounds__(256)
void pack_kernel(const float* __restrict__ W1,      // [64][120]
                 const float* __restrict__ W2,      // [64][64]
                 const float* __restrict__ W3)      // [64][64]
{
    const int t = blockIdx.x * 256 + threadIdx.x;
    if (t >= WPK_TOTAL) return;
    const float* Ws; int K, u = t;
    if (u < W1_PK)              { Ws = W1; K = 120; }
    else if (u < W1_PK + W2_PK) { Ws = W2; K = 64; u -= W1_PK; }
    else                        { Ws = W3; K = 64; u -= W1_PK + W2_PK; }
    const int kt = u >> 8, rem = u & 255;
    const int nt = rem >> 5, lane = rem & 31;
    const int g = lane >> 2, tg = lane & 3;
    const int k0 = kt * 8 + tg, n = nt * 8 + g;
    const float v0 = __ldg(Ws + n * K + k0);
    const float v1 = __ldg(Ws + n * K + k0 + 4);
    unsigned h0, l0, h1, l1;
    split_tf32(v0, h0, l0);
    split_tf32(v1, h1, l1);
    g_Wpack[t] = make_uint4(h0, h1, l0, l1);
}

// ===========================================================================
// Kernel 1: fused encode + tensor-core MLP
// ===========================================================================

// One layer: warp covers M-tile mt (rows 16mt..16mt+15) x N-tiles {2np,2np+1}.
// A from smem (tf32-rounded), B fragments via __ldg from g_Wpack.
template <int KSTEPS, int STRIDE>
__device__ __forceinline__ void mma_layer(const float* __restrict__ actIn,
                                          const uint4* __restrict__ wb,
                                          const float* __restrict__ bias,
                                          float*       __restrict__ actOut,
                                          int mt, int np, int lane) {
    const int g = lane >> 2, tg = lane & 3;
    const int rbase = mt * 16 + g;

    float acc[2][4];
    #pragma unroll
    for (int j = 0; j < 2; j++) {
        const int n0 = (np * 2 + j) * 8 + 2 * tg;
        const float bc0 = bias[n0], bc1 = bias[n0 + 1];
        acc[j][0] = bc0; acc[j][1] = bc1;
        acc[j][2] = bc0; acc[j][3] = bc1;
    }

    const unsigned* a0 = reinterpret_cast<const unsigned*>(
        actIn + (size_t)rbase * STRIDE);
    const unsigned* a1 = a0 + 8 * STRIDE;

    #pragma unroll
    for (int kt = 0; kt < KSTEPS; kt++) {
        const int kb = kt * 8;
        unsigned ah[4];
        ah[0] = a0[kb + tg];     ah[1] = a1[kb + tg];
        ah[2] = a0[kb + tg + 4]; ah[3] = a1[kb + tg + 4];

        #pragma unroll
        for (int j = 0; j < 2; j++) {
            const uint4 bw = __ldg(wb + (kt * 8 + np * 2 + j) * 32 + lane);
            mma_tf32(acc[j], ah, bw.x, bw.y);   // Ahi * Bhi
            mma_tf32(acc[j], ah, bw.z, bw.w);   // Ahi * Blo
        }
    }

    const int r0 = rbase, r1 = rbase + 8;
    #pragma unroll
    for (int j = 0; j < 2; j++) {
        const int n0 = (np * 2 + j) * 8 + 2 * tg;
        *reinterpret_cast<float2*>(actOut + r0 * 68 + n0) =
            make_float2(tf32r(fmaxf(acc[j][0], 0.0f)),
                        tf32r(fmaxf(acc[j][1], 0.0f)));
        *reinterpret_cast<float2*>(actOut + r1 * 68 + n0) =
            make_float2(tf32r(fmaxf(acc[j][2], 0.0f)),
                        tf32r(fmaxf(acc[j][3], 0.0f)));
    }
}

__global__ __launch_bounds__(THREADS, 2)
void rgbnet_fused(const float* __restrict__ x,        // [N,4]
                  const int*   __restrict__ ifirst,   // [N]
                  const float* __restrict__ emb,      // [6,2^19,4]
                  const float* __restrict__ b1, const float* __restrict__ b2,
                  const float* __restrict__ b3,
                  const float* __restrict__ W4, const float* __restrict__ b4,
                  float* __restrict__ out)             // [N,3]
{
    extern __shared__ float sh[];
    float* F  = sh + OFF_F;
    float* H  = sh + OFF_H;
    float* BS = sh + OFF_BS;

    const int tid  = threadIdx.x;
    const int ray0 = blockIdx.x * RPB;

    // ---- biases + W4 --------------------------------------------------------
    if (tid < 64) {
        BS[tid]       = __ldg(b1 + tid);
        BS[64 + tid]  = __ldg(b2 + tid);
        BS[128 + tid] = __ldg(b3 + tid);
    }
    if (tid < 4)   BS[192 + tid] = (tid < 3) ? __ldg(b4 + tid) : 0.0f;
    if (tid < 192) BS[196 + tid] = __ldg(W4 + tid);

    // ---- Phase E: encode -> F[64][132] (384 tasks) --------------------------
    if (tid < 6 * 64) {
        const int l   = tid >> 6;            // level, warp-uniform
        const int col = tid & 63;
        int ray = ray0 + col;
        ray = ray < NRAYS - 1 ? ray : NRAYS - 1;

        const float4 xr  = __ldg(reinterpret_cast<const float4*>(x) + ray);
        const int    if0 = __ldg(ifirst + ray);

        const int   R   = 4 << l;
        const float fR  = (float)R;
        const int   Rp1 = R + 1;
        const float4* __restrict__ tab =
            reinterpret_cast<const float4*>(emb) + (size_t)l * HSIZE;

        int    prev_key = -1;
        float4 cc[8];

        #pragma unroll
        for (int s = 0; s < 5; s++) {
            int sc = if0 + s - 2;
            sc = sc < 0 ? 0 : (sc > NSAMP - 1 ? NSAMP - 1 : sc);
            const float tt  = (float)sc * (1.0f / 299.0f);
            const float omt = 1.0f - tt;
            const float px = xr.x * omt + xr.z * tt;
            const float py = xr.y * omt + xr.w * tt;
            const float pz = tt;

            const float fx = px * fR, fy = py * fR, fz = pz * fR;
            const float flx = floorf(fx), fly = floorf(fy), flz = floorf(fz);
            const int ix = (int)flx, iy = (int)fly, iz = (int)flz;
            const float wx = fx - flx, wy = fy - fly, wz = fz - flz;

            const int key = ix | (iy << 10) | (iz << 20);
            if (key != prev_key) {
                prev_key = key;
                #pragma unroll
                for (int c = 0; c < 8; c++) {
                    const int bx = (c >> 2) & 1, by = (c >> 1) & 1, bz = c & 1;
                    int cx = ix + bx; cx = cx > R ? R : cx;
                    int cy = iy + by; cy = cy > R ? R : cy;
                    int cz = iz + bz; cz = cz > R ? R : cz;
                    const unsigned id_dense =
                        (unsigned)(cx + cy * Rp1 + cz * Rp1 * Rp1);
                    const unsigned id_hash =
                        ((unsigned)cx ^ ((unsigned)cy * 2654435761u)
                                     ^ ((unsigned)cz * 805459861u)) & HMASK;
                    const unsigned idx = (l == 5) ? id_hash : id_dense;
                    cc[c] = __ldg(tab + idx);
                }
            }

            float ax = 0.f, ay = 0.f, az = 0.f, aw = 0.f;
            #pragma unroll
            for (int c = 0; c < 8; c++) {
                const int bx = (c >> 2) & 1, by = (c >> 1) & 1, bz = c & 1;
                const float wgt = (bx ? wx : 1.0f - wx)
                                * (by ? wy : 1.0f - wy)
                                * (bz ? wz : 1.0f - wz);
                ax = fmaf(wgt, cc[c].x, ax);
                ay = fmaf(wgt, cc[c].y, ay);
                az = fmaf(wgt, cc[c].z, az);
                aw = fmaf(wgt, cc[c].w, aw);
            }

            const int kb = (s * 6 + l) * 4;
            *reinterpret_cast<float4*>(F + col * 132 + kb) =
                make_float4(tf32r(ax), tf32r(ay), tf32r(az), tf32r(aw));
        }
    }
    __syncthreads();     // F feats + biases visible

    const int lane = tid & 31;
    const int warp = tid >> 5;              // 0..15
    const int mt   = warp & 3;              // M-tile (rows 16mt..16mt+15)
    const int np   = warp >> 2;             // N-pair (outs 16np..16np+15)

    // ---- layer 1: F (K=120) -> H --------------------------------------------
    mma_layer<15, 132>(F, g_Wpack, BS, H, mt, np, lane);
    __syncthreads();

    // ---- layer 2: H -> F ------------------------------------------------------
    mma_layer<8, 68>(H, g_Wpack + W1_PK, BS + 64, F, mt, np, lane);
    __syncthreads();

    // ---- layer 3: F -> H ------------------------------------------------------
    mma_layer<8, 68>(F, g_Wpack + W1_PK + W2_PK, BS + 128, H, mt, np, lane);
    __syncthreads();

    // ---- layer 4: 64 -> 3, 8 threads per ray ----------------------------------
    {
        const int col = tid >> 3;            // 0..63
        const int kq  = tid & 7;             // k-eighth
        const float* hrow = H + col * 68 + kq * 8;
        const float* W4s  = BS + 196 + kq * 8;
        float a0 = 0.f, a1 = 0.f, a2 = 0.f;
        #pragma unroll
        for (int k = 0; k < 8; k++) {
            const float hv = hrow[k];
            a0 = fmaf(hv, W4s[k],       a0);
            a1 = fmaf(hv, W4s[64 + k],  a1);
            a2 = fmaf(hv, W4s[128 + k], a2);
        }
        a0 += __shfl_xor_sync(0xffffffffu, a0, 1);
        a1 += __shfl_xor_sync(0xffffffffu, a1, 1);
        a2 += __shfl_xor_sync(0xffffffffu, a2, 1);
        a0 += __shfl_xor_sync(0xffffffffu, a0, 2);
        a1 += __shfl_xor_sync(0xffffffffu, a1, 2);
        a2 += __shfl_xor_sync(0xffffffffu, a2, 2);
        a0 += __shfl_xor_sync(0xffffffffu, a0, 4);
        a1 += __shfl_xor_sync(0xffffffffu, a1, 4);
        a2 += __shfl_xor_sync(0xffffffffu, a2, 4);
        const int ray = ray0 + col;
        if (kq == 0 && col < RPB && ray < NRAYS) {
            float* o = out + (size_t)ray * 3;
            o[0] = a0 + BS[192];
            o[1] = a1 + BS[193];
            o[2] = a2 + BS[194];
        }
    }
}

extern "C" void kernel_launch(void* const* d_in, const int* in_sizes, int n_in,
                              void* d_out, int out_size) {
    const float* x    = (const float*)d_in[0];
    const int*   idxf = (const int*)  d_in[1];
    const float* emb  = (const float*)d_in[2];
    const float* W1   = (const float*)d_in[3];
    const float* b1   = (const float*)d_in[4];
    const float* W2   = (const float*)d_in[5];
    const float* b2   = (const float*)d_in[6];
    const float* W3   = (const float*)d_in[7];
    const float* b3   = (const float*)d_in[8];
    const float* W4   = (const float*)d_in[9];
    const float* b4   = (const float*)d_in[10];
    float* out = (float*)d_out;

    pack_kernel<<<(WPK_TOTAL + 255) / 256, 256>>>(W1, W2, W3);

    const size_t shbytes = (size_t)SH_FLOATS * sizeof(float);   // 52752 B
    cudaFuncSetAttribute(rgbnet_fused,
                         cudaFuncAttributeMaxDynamicSharedMemorySize,
                         (int)shbytes);
    rgbnet_fused<<<BLOCKS, THREADS, shbytes>>>(
        x, idxf, emb, b1, b2, b3, W4, b4, out);
}

// round 15
// speedup vs baseline: 1.1098x; 1.0976x over previous
#include <cuda_runtime.h>

// ---------------------------------------------------------------------------
// RgbNet, R14: 4 blocks/SM + PDL-overlapped weight pack.
//  K0 pack:  packs W1/W2/W3 into B-fragment hi/lo uint4 order (g_Wpack).
//  K1 fused: 586 blocks x 256 thr x 28 rays (32-col padded tile).
//            Launched with ProgrammaticStreamSerialization: encode phase
//            overlaps K0; cudaGridDependencySynchronize() before layer 1.
//            Layers: mma.sync m16n8k8 tf32, D = Ahi*Bhi + Ahi*Blo;
//            A from smem, B via __ldg (L1-resident, shared across blocks).
//            27KB smem, 64 regs -> 4 blocks/SM: phase bubbles overlap.
// ---------------------------------------------------------------------------

namespace {
constexpr int NRAYS   = 16384;
constexpr int NSAMP   = 300;
constexpr unsigned HSIZE = 1u << 19;
constexpr unsigned HMASK = HSIZE - 1u;

constexpr int THREADS = 256;     // 8 warps
constexpr int RPB     = 28;      // valid rays per block (32-col tile)
constexpr int BLOCKS  = (NRAYS + RPB - 1) / RPB;   // 586

// packed weight sizes (uint4 units): (K/8) * 8 ntiles * 32 lanes
constexpr int W1_PK = 15 * 8 * 32;   // 3840
constexpr int W2_PK = 8 * 8 * 32;    // 2048
constexpr int W3_PK = 8 * 8 * 32;    // 2048
constexpr int WPK_TOTAL = W1_PK + W2_PK + W3_PK;   // 7936

// shared layout (float offsets)
constexpr int OFF_F  = 0;                   // F [32][132] (feats / h2)
constexpr int OFF_H  = OFF_F + 32 * 132;    // H [32][68]  (h1 / h3)
constexpr int OFF_BS = OFF_H + 32 * 68;     // b1,b2,b3 (192) b4 (4) W4 (192)
constexpr int SH_FLOATS = OFF_BS + 388;     // 6788 fl = 27152 B
}

__device__ uint4 g_Wpack[WPK_TOTAL];

// ---- tf32 helpers -----------------------------------------------------------
__device__ __forceinline__ float tf32r(float v) {
    unsigned u;
    asm("cvt.rna.tf32.f32 %0, %1;" : "=r"(u) : "f"(v));
    return __uint_as_float(u);
}
__device__ __forceinline__ void split_tf32(float v, unsigned& hi, unsigned& lo) {
    asm("cvt.rna.tf32.f32 %0, %1;" : "=r"(hi) : "f"(v));
    const float lof = v - __uint_as_float(hi);
    asm("cvt.rna.tf32.f32 %0, %1;" : "=r"(lo) : "f"(lof));
}
__device__ __forceinline__ void mma_tf32(float* c, const unsigned* a,
                                         const unsigned b0, const unsigned b1) {
    asm volatile(
        "mma.sync.aligned.m16n8k8.row.col.f32.tf32.tf32.f32 "
        "{%0,%1,%2,%3}, {%4,%5,%6,%7}, {%8,%9}, {%0,%1,%2,%3};"
        : "+f"(c[0]), "+f"(c[1]), "+f"(c[2]), "+f"(c[3])
        : "r"(a[0]), "r"(a[1]), "r"(a[2]), "r"(a[3]), "r"(b0), "r"(b1));
}

// ===========================================================================
// Kernel 0: pack weights into B-fragment hi/lo uint4 order (once per replay)
// ===========================================================================
__global__ __launch_bounds__(256)
void pack_kernel(const float* __restrict__ W1,      // [64][120]
                 const float* __restrict__ W2,      // [64][64]
                 const float* __restrict__ W3)      // [64][64]
{
    const int t = blockIdx.x * 256 + threadIdx.x;
    if (t >= WPK_TOTAL) return;
    const float* Ws; int K, u = t;
    if (u < W1_PK)              { Ws = W1; K = 120; }
    else if (u < W1_PK + W2_PK) { Ws = W2; K = 64; u -= W1_PK; }
    else                        { Ws = W3; K = 64; u -= W1_PK + W2_PK; }
    const int kt = u >> 8, rem = u & 255;
    const int nt = rem >> 5, lane = rem & 31;
    const int g = lane >> 2, tg = lane & 3;
    const int k0 = kt * 8 + tg, n = nt * 8 + g;
    const float v0 = __ldg(Ws + n * K + k0);
    const float v1 = __ldg(Ws + n * K + k0 + 4);
    unsigned h0, l0, h1, l1;
    split_tf32(v0, h0, l0);
    split_tf32(v1, h1, l1);
    g_Wpack[t] = make_uint4(h0, h1, l0, l1);
}

// ===========================================================================
// Kernel 1: fused encode + tensor-core MLP
// ===========================================================================

// One layer: warp covers M-tile mt (rows 16mt..16mt+15) x N-tiles {2np,2np+1}.
// A from smem (tf32-rounded), B fragments via __ldg from g_Wpack.
template <int KSTEPS, int STRIDE>
__device__ __forceinline__ void mma_layer(const float* __restrict__ actIn,
                                          const uint4* __restrict__ wb,
                                          const float* __restrict__ bias,
                                          float*       __restrict__ actOut,
                                          int mt, int np, int lane) {
    const int g = lane >> 2, tg = lane & 3;
    const int rbase = mt * 16 + g;

    float acc[2][4];
    #pragma unroll
    for (int j = 0; j < 2; j++) {
        const int n0 = (np * 2 + j) * 8 + 2 * tg;
        const float bc0 = bias[n0], bc1 = bias[n0 + 1];
        acc[j][0] = bc0; acc[j][1] = bc1;
        acc[j][2] = bc0; acc[j][3] = bc1;
    }

    const unsigned* a0 = reinterpret_cast<const unsigned*>(
        actIn + (size_t)rbase * STRIDE);
    const unsigned* a1 = a0 + 8 * STRIDE;

    #pragma unroll
    for (int kt = 0; kt < KSTEPS; kt++) {
        const int kb = kt * 8;
        unsigned ah[4];
        ah[0] = a0[kb + tg];     ah[1] = a1[kb + tg];
        ah[2] = a0[kb + tg + 4]; ah[3] = a1[kb + tg + 4];

        #pragma unroll
        for (int j = 0; j < 2; j++) {
            const uint4 bw = __ldg(wb + (kt * 8 + np * 2 + j) * 32 + lane);
            mma_tf32(acc[j], ah, bw.x, bw.y);   // Ahi * Bhi
            mma_tf32(acc[j], ah, bw.z, bw.w);   // Ahi * Blo
        }
    }

    const int r0 = rbase, r1 = rbase + 8;
    #pragma unroll
    for (int j = 0; j < 2; j++) {
        const int n0 = (np * 2 + j) * 8 + 2 * tg;
        *reinterpret_cast<float2*>(actOut + r0 * 68 + n0) =
            make_float2(tf32r(fmaxf(acc[j][0], 0.0f)),
                        tf32r(fmaxf(acc[j][1], 0.0f)));
        *reinterpret_cast<float2*>(actOut + r1 * 68 + n0) =
            make_float2(tf32r(fmaxf(acc[j][2], 0.0f)),
                        tf32r(fmaxf(acc[j][3], 0.0f)));
    }
}

__global__ __launch_bounds__(THREADS, 4)
void rgbnet_fused(const float* __restrict__ x,        // [N,4]
                  const int*   __restrict__ ifirst,   // [N]
                  const float* __restrict__ emb,      // [6,2^19,4]
                  const float* __restrict__ b1, const float* __restrict__ b2,
                  const float* __restrict__ b3,
                  const float* __restrict__ W4, const float* __restrict__ b4,
                  float* __restrict__ out)             // [N,3]
{
    extern __shared__ float sh[];
    float* F  = sh + OFF_F;
    float* H  = sh + OFF_H;
    float* BS = sh + OFF_BS;

    const int tid  = threadIdx.x;
    const int ray0 = blockIdx.x * RPB;

    // ---- biases + W4 --------------------------------------------------------
    if (tid < 64) {
        BS[tid]       = __ldg(b1 + tid);
        BS[64 + tid]  = __ldg(b2 + tid);
        BS[128 + tid] = __ldg(b3 + tid);
    }
    if (tid < 4)   BS[192 + tid] = (tid < 3) ? __ldg(b4 + tid) : 0.0f;
    if (tid < 192) BS[196 + tid] = __ldg(W4 + tid);

    // ---- Phase E: encode -> F[32][132] (192 tasks; overlaps pack kernel) ---
    if (tid < 6 * 32) {
        const int l   = tid >> 5;            // level, warp-uniform
        const int col = tid & 31;
        int ray = ray0 + col;
        ray = ray < NRAYS - 1 ? ray : NRAYS - 1;

        const float4 xr  = __ldg(reinterpret_cast<const float4*>(x) + ray);
        const int    if0 = __ldg(ifirst + ray);

        const int   R   = 4 << l;
        const float fR  = (float)R;
        const int   Rp1 = R + 1;
        const float4* __restrict__ tab =
            reinterpret_cast<const float4*>(emb) + (size_t)l * HSIZE;

        int    prev_key = -1;
        float4 cc[8];

        #pragma unroll
        for (int s = 0; s < 5; s++) {
            int sc = if0 + s - 2;
            sc = sc < 0 ? 0 : (sc > NSAMP - 1 ? NSAMP - 1 : sc);
            const float tt  = (float)sc * (1.0f / 299.0f);
            const float omt = 1.0f - tt;
            const float px = xr.x * omt + xr.z * tt;
            const float py = xr.y * omt + xr.w * tt;
            const float pz = tt;

            const float fx = px * fR, fy = py * fR, fz = pz * fR;
            const float flx = floorf(fx), fly = floorf(fy), flz = floorf(fz);
            const int ix = (int)flx, iy = (int)fly, iz = (int)flz;
            const float wx = fx - flx, wy = fy - fly, wz = fz - flz;

            const int key = ix | (iy << 10) | (iz << 20);
            if (key != prev_key) {
                prev_key = key;
                #pragma unroll
                for (int c = 0; c < 8; c++) {
                    const int bx = (c >> 2) & 1, by = (c >> 1) & 1, bz = c & 1;
                    int cx = ix + bx; cx = cx > R ? R : cx;
                    int cy = iy + by; cy = cy > R ? R : cy;
                    int cz = iz + bz; cz = cz > R ? R : cz;
                    const unsigned id_dense =
                        (unsigned)(cx + cy * Rp1 + cz * Rp1 * Rp1);
                    const unsigned id_hash =
                        ((unsigned)cx ^ ((unsigned)cy * 2654435761u)
                                     ^ ((unsigned)cz * 805459861u)) & HMASK;
                    const unsigned idx = (l == 5) ? id_hash : id_dense;
                    cc[c] = __ldg(tab + idx);
                }
            }

            float ax = 0.f, ay = 0.f, az = 0.f, aw = 0.f;
            #pragma unroll
            for (int c = 0; c < 8; c++) {
                const int bx = (c >> 2) & 1, by = (c >> 1) & 1, bz = c & 1;
                const float wgt = (bx ? wx : 1.0f - wx)
                                * (by ? wy : 1.0f - wy)
                                * (bz ? wz : 1.0f - wz);
                ax = fmaf(wgt, cc[c].x, ax);
                ay = fmaf(wgt, cc[c].y, ay);
                az = fmaf(wgt, cc[c].z, az);
                aw = fmaf(wgt, cc[c].w, aw);
            }

            const int kb = (s * 6 + l) * 4;
            *reinterpret_cast<float4*>(F + col * 132 + kb) =
                make_float4(tf32r(ax), tf32r(ay), tf32r(az), tf32r(aw));
        }
    }

    // Wait for pack_kernel's g_Wpack writes (PDL dependency), then sync block.
    cudaGridDependencySynchronize();
    __syncthreads();     // F feats + biases visible

    const int lane = tid & 31;
    const int warp = tid >> 5;              // 0..7
    const int mt   = warp & 1;              // M-tile (rows 16mt..16mt+15)
    const int np   = warp >> 1;             // N-pair (outs 16np..16np+15)

    // ---- layer 1: F (K=120) -> H --------------------------------------------
    mma_layer<15, 132>(F, g_Wpack, BS, H, mt, np, lane);
    __syncthreads();

    // ---- layer 2: H -> F ------------------------------------------------------
    mma_layer<8, 68>(H, g_Wpack + W1_PK, BS + 64, F, mt, np, lane);
    __syncthreads();

    // ---- layer 3: F -> H ------------------------------------------------------
    mma_layer<8, 68>(F, g_Wpack + W1_PK + W2_PK, BS + 128, H, mt, np, lane);
    __syncthreads();

    // ---- layer 4: 64 -> 3, 8 threads per ray ----------------------------------
    {
        const int col = tid >> 3;            // 0..31
        const int kq  = tid & 7;             // k-eighth
        const float* hrow = H + col * 68 + kq * 8;
        const float* W4s  = BS + 196 + kq * 8;
        float a0 = 0.f, a1 = 0.f, a2 = 0.f;
        #pragma unroll
        for (int k = 0; k < 8; k++) {
            const float hv = hrow[k];
            a0 = fmaf(hv, W4s[k],       a0);
            a1 = fmaf(hv, W4s[64 + k],  a1);
            a2 = fmaf(hv, W4s[128 + k], a2);
        }
        a0 += __shfl_xor_sync(0xffffffffu, a0, 1);
        a1 += __shfl_xor_sync(0xffffffffu, a1, 1);
        a2 += __shfl_xor_sync(0xffffffffu, a2, 1);
        a0 += __shfl_xor_sync(0xffffffffu, a0, 2);
        a1 += __shfl_xor_sync(0xffffffffu, a1, 2);
        a2 += __shfl_xor_sync(0xffffffffu, a2, 2);
        a0 += __shfl_xor_sync(0xffffffffu, a0, 4);
        a1 += __shfl_xor_sync(0xffffffffu, a1, 4);
        a2 += __shfl_xor_sync(0xffffffffu, a2, 4);
        const int ray = ray0 + col;
        if (kq == 0 && col < RPB && ray < NRAYS) {
            float* o = out + (size_t)ray * 3;
            o[0] = a0 + BS[192];
            o[1] = a1 + BS[193];
            o[2] = a2 + BS[194];
        }
    }
}

extern "C" void kernel_launch(void* const* d_in, const int* in_sizes, int n_in,
                              void* d_out, int out_size) {
    const float* x    = (const float*)d_in[0];
    const int*   idxf = (const int*)  d_in[1];
    const float* emb  = (const float*)d_in[2];
    const float* W1   = (const float*)d_in[3];
    const float* b1   = (const float*)d_in[4];
    const float* W2   = (const float*)d_in[5];
    const float* b2   = (const float*)d_in[6];
    const float* W3   = (const float*)d_in[7];
    const float* b3   = (const float*)d_in[8];
    const float* W4   = (const float*)d_in[9];
    const float* b4   = (const float*)d_in[10];
    float* out = (float*)d_out;

    pack_kernel<<<(WPK_TOTAL + 255) / 256, 256>>>(W1, W2, W3);

    const size_t shbytes = (size_t)SH_FLOATS * sizeof(float);   // 27152 B
    cudaFuncSetAttribute(rgbnet_fused,
                         cudaFuncAttributeMaxDynamicSharedMemorySize,
                         (int)shbytes);

    // PDL: fused kernel launches while pack runs; it synchronizes on the
    // grid dependency (cudaGridDependencySynchronize) before reading g_Wpack.
    cudaLaunchConfig_t cfg = {};
    cfg.gridDim  = dim3(BLOCKS, 1, 1);
    cfg.blockDim = dim3(THREADS, 1, 1);
    cfg.dynamicSmemBytes = shbytes;
    cudaLaunchAttribute attrs[1];
    attrs[0].id = cudaLaunchAttributeProgrammaticStreamSerialization;
    attrs[0].val.programmaticStreamSerializationAllowed = 1;
    cfg.attrs = attrs;
    cfg.numAttrs = 1;

    cudaLaunchKernelEx(&cfg, rgbnet_fused,
                       x, idxf, emb, b1, b2, b3, W4, b4, out);
}

// round 17
// speedup vs baseline: 1.2277x; 1.1062x over previous
#include <cuda_runtime.h>

// ---------------------------------------------------------------------------
// RgbNet, R16: 16-ray blocks (128 thr), 8 blocks/SM, plain __syncthreads.
//  K0 pack:  packs W1/W2/W3 into B-fragment hi/lo uint4 order (g_Wpack).
//  K1 fused: 1024 blocks x 128 thr x 16 rays (exact, no padding).
//            PDL overlaps K0 with encode phase.
//            Layers: mma.sync m16n8k8 tf32, D = Ahi*Bhi + Ahi*Blo;
//            A from smem, B via __ldg (L1-resident, shared across blocks).
//            14.4KB smem, 64 regs -> 8 independent pipelines per SM.
// ---------------------------------------------------------------------------

namespace {
constexpr int NRAYS   = 16384;
constexpr int NSAMP   = 300;
constexpr unsigned HSIZE = 1u << 19;
constexpr unsigned HMASK = HSIZE - 1u;

constexpr int THREADS = 128;     // 4 warps
constexpr int RPB     = 16;      // rays per block (exact tile)
constexpr int BLOCKS  = NRAYS / RPB;   // 1024

// packed weight sizes (uint4 units): (K/8) * 8 ntiles * 32 lanes
constexpr int W1_PK = 15 * 8 * 32;   // 3840
constexpr int W2_PK = 8 * 8 * 32;    // 2048
constexpr int W3_PK = 8 * 8 * 32;    // 2048
constexpr int WPK_TOTAL = W1_PK + W2_PK + W3_PK;   // 7936

// shared layout (float offsets)
constexpr int OFF_F  = 0;                   // F [16][132] (feats / h2)
constexpr int OFF_H  = OFF_F + 16 * 132;    // H [16][68]  (h1 / h3)
constexpr int OFF_BS = OFF_H + 16 * 68;     // b1,b2,b3 (192) b4 (4) W4 (192)
constexpr int SH_FLOATS = OFF_BS + 388;     // 3588 fl = 14352 B
}

__device__ uint4 g_Wpack[WPK_TOTAL];

// ---- tf32 helpers -----------------------------------------------------------
__device__ __forceinline__ float tf32r(float v) {
    unsigned u;
    asm("cvt.rna.tf32.f32 %0, %1;" : "=r"(u) : "f"(v));
    return __uint_as_float(u);
}
__device__ __forceinline__ void split_tf32(float v, unsigned& hi, unsigned& lo) {
    asm("cvt.rna.tf32.f32 %0, %1;" : "=r"(hi) : "f"(v));
    const float lof = v - __uint_as_float(hi);
    asm("cvt.rna.tf32.f32 %0, %1;" : "=r"(lo) : "f"(lof));
}
__device__ __forceinline__ void mma_tf32(float* c, const unsigned* a,
                                         const unsigned b0, const unsigned b1) {
    asm volatile(
        "mma.sync.aligned.m16n8k8.row.col.f32.tf32.tf32.f32 "
        "{%0,%1,%2,%3}, {%4,%5,%6,%7}, {%8,%9}, {%0,%1,%2,%3};"
        : "+f"(c[0]), "+f"(c[1]), "+f"(c[2]), "+f"(c[3])
        : "r"(a[0]), "r"(a[1]), "r"(a[2]), "r"(a[3]), "r"(b0), "r"(b1));
}

// ===========================================================================
// Kernel 0: pack weights into B-fragment hi/lo uint4 order (once per replay)
// ===========================================================================
__global__ __launch_bounds__(256)
void pack_kernel(const float* __restrict__ W1,      // [64][120]
                 const float* __restrict__ W2,      // [64][64]
                 const float* __restrict__ W3)      // [64][64]
{
    const int t = blockIdx.x * 256 + threadIdx.x;
    if (t >= WPK_TOTAL) return;
    const float* Ws; int K, u = t;
    if (u < W1_PK)              { Ws = W1; K = 120; }
    else if (u < W1_PK + W2_PK) { Ws = W2; K = 64; u -= W1_PK; }
    else                        { Ws = W3; K = 64; u -= W1_PK + W2_PK; }
    const int kt = u >> 8, rem = u & 255;
    const int nt = rem >> 5, lane = rem & 31;
    const int g = lane >> 2, tg = lane & 3;
    const int k0 = kt * 8 + tg, n = nt * 8 + g;
    const float v0 = __ldg(Ws + n * K + k0);
    const float v1 = __ldg(Ws + n * K + k0 + 4);
    unsigned h0, l0, h1, l1;
    split_tf32(v0, h0, l0);
    split_tf32(v1, h1, l1);
    g_Wpack[t] = make_uint4(h0, h1, l0, l1);
}

// ===========================================================================
// Kernel 1: fused encode + tensor-core MLP (16-ray block)
// ===========================================================================

// One layer: warp covers M-tile 0 (rows 0-15) x N-tiles {2np, 2np+1}.
template <int KSTEPS, int STRIDE>
__device__ __forceinline__ void mma_layer(const float* __restrict__ actIn,
                                          const uint4* __restrict__ wb,
                                          const float* __restrict__ bias,
                                          float*       __restrict__ actOut,
                                          int np, int lane) {
    const int g = lane >> 2, tg = lane & 3;

    float acc[2][4];
    #pragma unroll
    for (int j = 0; j < 2; j++) {
        const int n0 = (np * 2 + j) * 8 + 2 * tg;
        const float bc0 = bias[n0], bc1 = bias[n0 + 1];
        acc[j][0] = bc0; acc[j][1] = bc1;
        acc[j][2] = bc0; acc[j][3] = bc1;
    }

    const unsigned* a0 = reinterpret_cast<const unsigned*>(
        actIn + (size_t)g * STRIDE);
    const unsigned* a1 = a0 + 8 * STRIDE;

    #pragma unroll
    for (int kt = 0; kt < KSTEPS; kt++) {
        const int kb = kt * 8;
        unsigned ah[4];
        ah[0] = a0[kb + tg];     ah[1] = a1[kb + tg];
        ah[2] = a0[kb + tg + 4]; ah[3] = a1[kb + tg + 4];

        #pragma unroll
        for (int j = 0; j < 2; j++) {
            const uint4 bw = __ldg(wb + (kt * 8 + np * 2 + j) * 32 + lane);
            mma_tf32(acc[j], ah, bw.x, bw.y);   // Ahi * Bhi
            mma_tf32(acc[j], ah, bw.z, bw.w);   // Ahi * Blo
        }
    }

    const int r0 = g, r1 = g + 8;
    #pragma unroll
    for (int j = 0; j < 2; j++) {
        const int n0 = (np * 2 + j) * 8 + 2 * tg;
        *reinterpret_cast<float2*>(actOut + r0 * 68 + n0) =
            make_float2(tf32r(fmaxf(acc[j][0], 0.0f)),
                        tf32r(fmaxf(acc[j][1], 0.0f)));
        *reinterpret_cast<float2*>(actOut + r1 * 68 + n0) =
            make_float2(tf32r(fmaxf(acc[j][2], 0.0f)),
                        tf32r(fmaxf(acc[j][3], 0.0f)));
    }
}

__global__ __launch_bounds__(THREADS, 8)
void rgbnet_fused(const float* __restrict__ x,        // [N,4]
                  const int*   __restrict__ ifirst,   // [N]
                  const float* __restrict__ emb,      // [6,2^19,4]
                  const float* __restrict__ b1, const float* __restrict__ b2,
                  const float* __restrict__ b3,
                  const float* __restrict__ W4, const float* __restrict__ b4,
                  float* __restrict__ out)             // [N,3]
{
    extern __shared__ float sh[];
    float* F  = sh + OFF_F;
    float* H  = sh + OFF_H;
    float* BS = sh + OFF_BS;

    const int tid  = threadIdx.x;
    const int ray0 = blockIdx.x * RPB;

    // ---- biases + W4 --------------------------------------------------------
    if (tid < 64) {
        BS[tid]       = __ldg(b1 + tid);
        BS[64 + tid]  = __ldg(b2 + tid);
    }
    else if (tid < 128) {
        BS[64 + tid]  = __ldg(b3 + tid - 64);          // [128,192)
    }
    if (tid < 4) BS[192 + tid] = (tid < 3) ? __ldg(b4 + tid) : 0.0f;
    // W4 (192 floats) on 128 threads: two strided passes
    BS[196 + tid] = __ldg(W4 + tid);
    if (tid < 64) BS[196 + 128 + tid] = __ldg(W4 + 128 + tid);

    // ---- Phase E: encode -> F[16][132] (96 tasks on 128 threads) ------------
    if (tid < 96) {
        const int l   = tid >> 4;            // level 0..5 (mixed in warp)
        const int col = tid & 15;
        const int ray = ray0 + col;

        const float4 xr  = __ldg(reinterpret_cast<const float4*>(x) + ray);
        const int    if0 = __ldg(ifirst + ray);

        const int   R   = 4 << l;
        const float fR  = (float)R;
        const int   Rp1 = R + 1;
        const float4* __restrict__ tab =
            reinterpret_cast<const float4*>(emb) + (size_t)l * HSIZE;

        int    prev_key = -1;
        float4 cc[8];

        #pragma unroll
        for (int s = 0; s < 5; s++) {
            int sc = if0 + s - 2;
            sc = sc < 0 ? 0 : (sc > NSAMP - 1 ? NSAMP - 1 : sc);
            const float tt  = (float)sc * (1.0f / 299.0f);
            const float omt = 1.0f - tt;
            const float px = xr.x * omt + xr.z * tt;
            const float py = xr.y * omt + xr.w * tt;
            const float pz = tt;

            const float fx = px * fR, fy = py * fR, fz = pz * fR;
            const float flx = floorf(fx), fly = floorf(fy), flz = floorf(fz);
            const int ix = (int)flx, iy = (int)fly, iz = (int)flz;
            const float wx = fx - flx, wy = fy - fly, wz = fz - flz;

            const int key = ix | (iy << 10) | (iz << 20);
            if (key != prev_key) {
                prev_key = key;
                #pragma unroll
                for (int c = 0; c < 8; c++) {
                    const int bx = (c >> 2) & 1, by = (c >> 1) & 1, bz = c & 1;
                    int cx = ix + bx; cx = cx > R ? R : cx;
                    int cy = iy + by; cy = cy > R ? R : cy;
                    int cz = iz + bz; cz = cz > R ? R : cz;
                    const unsigned id_dense =
                        (unsigned)(cx + cy * Rp1 + cz * Rp1 * Rp1);
                    const unsigned id_hash =
                        ((unsigned)cx ^ ((unsigned)cy * 2654435761u)
                                     ^ ((unsigned)cz * 805459861u)) & HMASK;
                    const unsigned idx = (l == 5) ? id_hash : id_dense;
                    cc[c] = __ldg(tab + idx);
                }
            }

            float ax = 0.f, ay = 0.f, az = 0.f, aw = 0.f;
            #pragma unroll
            for (int c = 0; c < 8; c++) {
                const int bx = (c >> 2) & 1, by = (c >> 1) & 1, bz = c & 1;
                const float wgt = (bx ? wx : 1.0f - wx)
                                * (by ? wy : 1.0f - wy)
                                * (bz ? wz : 1.0f - wz);
                ax = fmaf(wgt, cc[c].x, ax);
                ay = fmaf(wgt, cc[c].y, ay);
                az = fmaf(wgt, cc[c].z, az);
                aw = fmaf(wgt, cc[c].w, aw);
            }

            const int kb = (s * 6 + l) * 4;
            *reinterpret_cast<float4*>(F + col * 132 + kb) =
                make_float4(tf32r(ax), tf32r(ay), tf32r(az), tf32r(aw));
        }
    }

    // Wait for pack_kernel's g_Wpack writes (PDL), then block sync.
    cudaGridDependencySynchronize();
    __syncthreads();     // feats + biases visible

    const int lane = tid & 31;
    const int np   = tid >> 5;               // warp 0..3 = N-pair

    // ---- layer 1: F (K=120) -> H --------------------------------------------
    mma_layer<15, 132>(F, g_Wpack, BS, H, np, lane);
    __syncthreads();

    // ---- layer 2: H -> F ------------------------------------------------------
    mma_layer<8, 68>(H, g_Wpack + W1_PK, BS + 64, F, np, lane);
    __syncthreads();

    // ---- layer 3: F -> H ------------------------------------------------------
    mma_layer<8, 68>(F, g_Wpack + W1_PK + W2_PK, BS + 128, H, np, lane);
    __syncthreads();

    // ---- layer 4: 64 -> 3, 8 threads per ray ----------------------------------
    {
        const int col = tid >> 3;            // 0..15
        const int kq  = tid & 7;             // k-eighth
        const float* hrow = H + col * 68 + kq * 8;
        const float* W4s  = BS + 196 + kq * 8;
        float a0 = 0.f, a1 = 0.f, a2 = 0.f;
        #pragma unroll
        for (int k = 0; k < 8; k++) {
            const float hv = hrow[k];
            a0 = fmaf(hv, W4s[k],       a0);
            a1 = fmaf(hv, W4s[64 + k],  a1);
            a2 = fmaf(hv, W4s[128 + k], a2);
        }
        a0 += __shfl_xor_sync(0xffffffffu, a0, 1);
        a1 += __shfl_xor_sync(0xffffffffu, a1, 1);
        a2 += __shfl_xor_sync(0xffffffffu, a2, 1);
        a0 += __shfl_xor_sync(0xffffffffu, a0, 2);
        a1 += __shfl_xor_sync(0xffffffffu, a1, 2);
        a2 += __shfl_xor_sync(0xffffffffu, a2, 2);
        a0 += __shfl_xor_sync(0xffffffffu, a0, 4);
        a1 += __shfl_xor_sync(0xffffffffu, a1, 4);
        a2 += __shfl_xor_sync(0xffffffffu, a2, 4);
        if (kq == 0) {
            float* o = out + (size_t)(ray0 + col) * 3;
            o[0] = a0 + BS[192];
            o[1] = a1 + BS[193];
            o[2] = a2 + BS[194];
        }
    }
}

extern "C" void kernel_launch(void* const* d_in, const int* in_sizes, int n_in,
                              void* d_out, int out_size) {
    const float* x    = (const float*)d_in[0];
    const int*   idxf = (const int*)  d_in[1];
    const float* emb  = (const float*)d_in[2];
    const float* W1   = (const float*)d_in[3];
    const float* b1   = (const float*)d_in[4];
    const float* W2   = (const float*)d_in[5];
    const float* b2   = (const float*)d_in[6];
    const float* W3   = (const float*)d_in[7];
    const float* b3   = (const float*)d_in[8];
    const float* W4   = (const float*)d_in[9];
    const float* b4   = (const float*)d_in[10];
    float* out = (float*)d_out;

    pack_kernel<<<(WPK_TOTAL + 255) / 256, 256>>>(W1, W2, W3);

    const size_t shbytes = (size_t)SH_FLOATS * sizeof(float);   // 14352 B
    cudaFuncSetAttribute(rgbnet_fused,
                         cudaFuncAttributeMaxDynamicSharedMemorySize,
                         (int)shbytes);

    cudaLaunchConfig_t cfg = {};
    cfg.gridDim  = dim3(BLOCKS, 1, 1);
    cfg.blockDim = dim3(THREADS, 1, 1);
    cfg.dynamicSmemBytes = shbytes;
    cudaLaunchAttribute attrs[1];
    attrs[0].id = cudaLaunchAttributeProgrammaticStreamSerialization;
    attrs[0].val.programmaticStreamSerializationAllowed = 1;
    cfg.attrs = attrs;
    cfg.numAttrs = 1;

    cudaLaunchKernelEx(&cfg, rgbnet_fused,
                       x, idxf, emb, b1, b2, b3, W4, b4, out);
}